// round 1
// baseline (speedup 1.0000x reference)
#include <cuda_runtime.h>
#include <cuda_bf16.h>

// ---------------- problem constants ----------------
#define BATCH   4
#define NPTS    32768
#define NCLS    3
#define KSEL    4096          // NMS_PRE_MAXSIZE
#define KPOST   512           // NMS_POST_MAXSIZE
#define NWORDS  64            // 4096 / 64
#define NW1     16            // first-stage scan: 1024 boxes
#define CHUNK   16384
#define SORT_T  1024

#define ROIS_ELEMS   (BATCH * KPOST * 7)          // 14336
#define SC_OFF       (ROIS_ELEMS)                 // 14336
#define LB_OFF       (ROIS_ELEMS + BATCH * KPOST) // 16384

// ---------------- device scratch (no allocations allowed) ----------------
__device__ unsigned long long g_keys[BATCH][NPTS];          // 1 MB
__device__ float4             g_box4[BATCH][KSEL];          // x1,y1,x2,y2
__device__ float              g_area[BATCH][KSEL];
__device__ float              g_rois[BATCH][KSEL][7];
__device__ float              g_scores[BATCH][KSEL];
__device__ unsigned char      g_labels[BATCH][KSEL];
__device__ unsigned long long g_mask[BATCH][KSEL * NWORDS]; // 8 MB
__device__ unsigned long long g_accept[BATCH][NWORDS];
__device__ int                g_done[BATCH];

// ---------------- sort: keys + local bitonic (chunk in smem) ----------------
// phase 0: build keys, full bitonic sort of each 16384-chunk (k = 2..16384)
// phase 1: final merge substeps (k = 32768, j = 8192..1), all within chunk
__global__ void __launch_bounds__(SORT_T)
k_sort_local(const float* __restrict__ cls, int phase) {
    extern __shared__ unsigned long long sk[];
    const int b = blockIdx.y, c = blockIdx.x, t = threadIdx.x;
    const int base = c * CHUNK;

    if (phase == 0) {
        for (int e = t; e < CHUNK; e += SORT_T) {
            int gi = base + e;
            const float* cp = cls + ((size_t)b * NPTS + gi) * NCLS;
            float s = fmaxf(fmaxf(cp[0], cp[1]), cp[2]);
            unsigned u = __float_as_uint(s);
            u = (u & 0x80000000u) ? ~u : (u | 0x80000000u);  // order-preserving
            sk[e] = ((unsigned long long)u << 32) |
                    (unsigned long long)(0xFFFFFFFFu - (unsigned)gi);
        }
    } else {
        for (int e = t; e < CHUNK; e += SORT_T) sk[e] = g_keys[b][base + e];
    }
    __syncthreads();

    if (phase == 0) {
        for (int k = 2; k <= CHUNK; k <<= 1) {
            for (int j = k >> 1; j >= 1; j >>= 1) {
                for (int p = t; p < CHUNK / 2; p += SORT_T) {
                    int i = ((p & ~(j - 1)) << 1) | (p & (j - 1));
                    int l = i + j;
                    unsigned long long a = sk[i], bb = sk[l];
                    bool desc = (((base + i) & k) == 0);     // global index bit
                    if (desc ? (a < bb) : (a > bb)) { sk[i] = bb; sk[l] = a; }
                }
                __syncthreads();
            }
        }
    } else {
        for (int j = CHUNK >> 1; j >= 1; j >>= 1) {
            for (int p = t; p < CHUNK / 2; p += SORT_T) {
                int i = ((p & ~(j - 1)) << 1) | (p & (j - 1));
                int l = i + j;
                unsigned long long a = sk[i], bb = sk[l];
                if (a < bb) { sk[i] = bb; sk[l] = a; }       // descending everywhere
            }
            __syncthreads();
        }
    }
    for (int e = t; e < CHUNK; e += SORT_T) g_keys[b][base + e] = sk[e];
}

// k = 32768, j = 16384 global exchange (descending)
__global__ void k_sort_gstep() {
    int p = blockIdx.x * blockDim.x + threadIdx.x;  // 0..16383
    int b = blockIdx.y;
    unsigned long long a = g_keys[b][p], c = g_keys[b][p + CHUNK];
    if (a < c) { g_keys[b][p] = c; g_keys[b][p + CHUNK] = a; }
}

// ---------------- gather top-4096 boxes + precompute IOU fields ----------------
__global__ void k_gather(const float* __restrict__ boxes,
                         const float* __restrict__ cls) {
    int g = blockIdx.x * blockDim.x + threadIdx.x;
    if (g >= BATCH * KSEL) return;
    int b = g >> 12, r = g & (KSEL - 1);
    unsigned long long key = g_keys[b][r];
    int idx = (int)(0xFFFFFFFFu - (unsigned)key);

    const float* bx = boxes + ((size_t)b * NPTS + idx) * 7;
    float v0 = bx[0], v1 = bx[1], v2 = bx[2], v3 = bx[3],
          v4 = bx[4], v5 = bx[5], v6 = bx[6];
    float* ro = &g_rois[b][r][0];
    ro[0] = v0; ro[1] = v1; ro[2] = v2; ro[3] = v3;
    ro[4] = v4; ro[5] = v5; ro[6] = v6;

    const float* cp = cls + ((size_t)b * NPTS + idx) * NCLS;
    float c0 = cp[0], c1 = cp[1], c2 = cp[2];
    float s = c0; int lab = 0;
    if (c1 > s) { s = c1; lab = 1; }
    if (c2 > s) { s = c2; lab = 2; }
    g_scores[b][r] = s;
    g_labels[b][r] = (unsigned char)lab;

    // match reference rounding exactly: x1 = x - 0.5*dx (mul then sub, no FMA)
    float hx = __fmul_rn(0.5f, v3), hy = __fmul_rn(0.5f, v4);
    float x1 = __fsub_rn(v0, hx), x2 = __fadd_rn(v0, hx);
    float y1 = __fsub_rn(v1, hy), y2 = __fadd_rn(v1, hy);
    g_box4[b][r] = make_float4(x1, y1, x2, y2);
    g_area[b][r] = __fmul_rn(v3, v4);
}

// ---------------- suppression bitmask ----------------
// stage 0: only row/col blocks < NW1 (first 1024 boxes)
// stage 1: everything else; early-exit per batch when stage-1 scan succeeded
__global__ void __launch_bounds__(64)
k_mask(int stage) {
    int cb = blockIdx.x, rb = blockIdx.y, b = blockIdx.z;
    if (cb < rb) return;
    if (stage) {
        if (g_done[b]) return;
        if (cb < NW1 && rb < NW1) return;   // already done by stage 0
    }
    __shared__ float4 sb[64];
    __shared__ float  sa[64];
    int t = threadIdx.x;
    sb[t] = g_box4[b][cb * 64 + t];
    sa[t] = g_area[b][cb * 64 + t];
    __syncthreads();

    int i = rb * 64 + t;
    float4 me = g_box4[b][i];
    float  a  = g_area[b][i];
    unsigned long long m = 0;
    int j0 = (cb == rb) ? (t + 1) : 0;      // only j > i suppressed
    for (int jj = j0; jj < 64; jj++) {
        float4 o = sb[jj];
        float ix = __fsub_rn(fminf(me.z, o.z), fmaxf(me.x, o.x));
        float iy = __fsub_rn(fminf(me.w, o.w), fmaxf(me.y, o.y));
        if (ix > 0.0f && iy > 0.0f) {       // rare: only then pay the divide
            float inter = __fmul_rn(ix, iy);
            float denom = __fadd_rn(__fsub_rn(__fadd_rn(a, sa[jj]), inter), 1e-6f);
            if (__fdiv_rn(inter, denom) > 0.7f) m |= (1ull << jj);
        }
    }
    g_mask[b][(size_t)i * NWORDS + cb] = m;
}

// ---------------- sequential greedy scan, word-chunked ----------------
__global__ void __launch_bounds__(64)
k_scan(int full) {
    int b = blockIdx.x, t = threadIdx.x;
    if (full && g_done[b]) return;
    const int NW = full ? NWORDS : NW1;

    __shared__ unsigned long long remv[NWORDS], acc_s[NWORDS], diag[64];
    remv[t] = 0ull;
    __syncthreads();

    for (int w = 0; w < NW; w++) {
        // parallel fetch of the diagonal block column: diag[bit] = mask[w*64+bit][w]
        diag[t] = g_mask[b][(size_t)(w * 64 + t) * NWORDS + w];
        __syncthreads();
        if (t == w) {
            unsigned long long d[64];
#pragma unroll
            for (int q = 0; q < 64; q++) d[q] = diag[q];    // into registers
            unsigned long long rem = remv[w], acc = 0ull;
#pragma unroll
            for (int bit = 0; bit < 64; bit++) {            // serial greedy, reg-only
                if (!((rem >> bit) & 1ull)) { acc |= (1ull << bit); rem |= d[bit]; }
            }
            acc_s[w] = acc;
        }
        __syncthreads();
        if (t > w && t < NW) {
            unsigned long long aa = acc_s[w];
            unsigned long long r = remv[t];
            while (aa) {                                    // OR rows of accepted i
                int bit = __ffsll((long long)aa) - 1;
                aa &= aa - 1;
                r |= g_mask[b][(size_t)(w * 64 + bit) * NWORDS + t];
            }
            remv[t] = r;
        }
        __syncthreads();
    }

    g_accept[b][t] = (t < NW) ? acc_s[t] : 0ull;
    if (t == 0 && !full) {
        int cnt = 0;
        for (int w = 0; w < NW; w++) cnt += __popcll(acc_s[w]);
        g_done[b] = (cnt >= KPOST);   // enough survivors in first 1024 -> skip full pass
    }
}

// ---------------- output ----------------
__global__ void k_zero(float* out, int n) {
    int i = blockIdx.x * blockDim.x + threadIdx.x;
    if (i < n) out[i] = 0.0f;
}

__global__ void __launch_bounds__(64)
k_compact(float* __restrict__ out) {
    int b = blockIdx.x, t = threadIdx.x;
    __shared__ unsigned long long acc[NWORDS];
    __shared__ int pref[NWORDS];
    acc[t] = g_accept[b][t];
    __syncthreads();
    if (t == 0) {
        int s = 0;
        for (int w = 0; w < NWORDS; w++) { pref[w] = s; s += __popcll(acc[w]); }
    }
    __syncthreads();

    unsigned long long a = acc[t];
    int rank = pref[t];
    while (a && rank < KPOST) {
        int bit = __ffsll((long long)a) - 1;
        a &= a - 1;
        int i = t * 64 + bit;
        const float* ro = &g_rois[b][i][0];
        int obase = (b * KPOST + rank) * 7;
#pragma unroll
        for (int c = 0; c < 7; c++) out[obase + c] = ro[c];
        out[SC_OFF + b * KPOST + rank] = g_scores[b][i];
        out[LB_OFF + b * KPOST + rank] = (float)(g_labels[b][i] + 1);
        rank++;
    }
}

// ---------------- launch ----------------
extern "C" void kernel_launch(void* const* d_in, const int* in_sizes, int n_in,
                              void* d_out, int out_size) {
    const float* boxes = (const float*)d_in[0];
    const float* cls   = (const float*)d_in[1];
    // disambiguate input order by element counts (boxes: B*N*7, cls: B*N*3)
    if (n_in >= 2 && in_sizes[0] == BATCH * NPTS * NCLS) {
        boxes = (const float*)d_in[1];
        cls   = (const float*)d_in[0];
    }
    float* out = (float*)d_out;

    cudaFuncSetAttribute(k_sort_local,
                         cudaFuncAttributeMaxDynamicSharedMemorySize,
                         CHUNK * (int)sizeof(unsigned long long));

    // sort (3 launches)
    k_sort_local<<<dim3(2, BATCH), SORT_T, CHUNK * sizeof(unsigned long long)>>>(cls, 0);
    k_sort_gstep<<<dim3(CHUNK / 256, BATCH), 256>>>();
    k_sort_local<<<dim3(2, BATCH), SORT_T, CHUNK * sizeof(unsigned long long)>>>(cls, 1);

    // gather + precompute
    k_gather<<<(BATCH * KSEL + 255) / 256, 256>>>(boxes, cls);

    // staged NMS: first 1024 boxes, then (rarely) the full 4096
    k_mask<<<dim3(NW1, NW1, BATCH), 64>>>(0);
    k_scan<<<BATCH, 64>>>(0);
    k_mask<<<dim3(NWORDS, NWORDS, BATCH), 64>>>(1);
    k_scan<<<BATCH, 64>>>(1);

    // outputs
    k_zero<<<(out_size + 255) / 256, 256>>>(out, out_size);
    k_compact<<<BATCH, 64>>>(out);
}

// round 3
// speedup vs baseline: 1.2848x; 1.2848x over previous
#include <cuda_runtime.h>
#include <cuda_bf16.h>

// ---------------- problem constants ----------------
#define BATCH   4
#define NPTS    32768
#define NCLS    3
#define KSEL    4096          // NMS_PRE_MAXSIZE
#define KPOST   512           // NMS_POST_MAXSIZE
#define NWORDS  64            // 4096 / 64
#define NW1     16            // first-stage scan: 1024 boxes
#define NBUCK   65536         // 16-bit score-radix buckets

#define ROIS_ELEMS   (BATCH * KPOST * 7)          // 14336
#define SC_OFF       (ROIS_ELEMS)                 // 14336
#define LB_OFF       (ROIS_ELEMS + BATCH * KPOST) // 16384

// ---------------- device scratch (no allocations allowed) ----------------
__device__ unsigned long long g_keyfull[BATCH][NPTS];       // 1 MB
__device__ unsigned long long g_cand[BATCH][NPTS];          // 1 MB (bucket-grouped)
__device__ unsigned long long g_topk[BATCH][KSEL];          // descending top-4096 keys
__device__ int                g_hist[BATCH][NBUCK];         // 1 MB
__device__ int                g_base[BATCH][NBUCK];         // 1 MB
__device__ int                g_cnt [BATCH][NBUCK];         // scatter offsets
__device__ int                g_candcnt[BATCH];

__device__ float4             g_box4[BATCH][KSEL];          // x1,y1,x2,y2
__device__ float              g_area[BATCH][KSEL];
__device__ float              g_rois[BATCH][KSEL][7];
__device__ float              g_scores[BATCH][KSEL];
__device__ unsigned char      g_labels[BATCH][KSEL];
__device__ unsigned long long g_mask[BATCH][KSEL * NWORDS]; // 8 MB
__device__ unsigned long long g_accept[BATCH][NWORDS];
__device__ int                g_done[BATCH];

// ---------------- order-preserving float->uint transform ----------------
__device__ __forceinline__ unsigned f2ord(float s) {
    unsigned u = __float_as_uint(s);
    return (u & 0x80000000u) ? ~u : (u | 0x80000000u);
}

// ---------------- Kz: zero per-replay state (vectorized) ----------------
__global__ void k_zero_state() {
    int i = blockIdx.x * blockDim.x + threadIdx.x;
    int stride = gridDim.x * blockDim.x;
    int4 z = make_int4(0, 0, 0, 0);
    int4* h4 = (int4*)g_hist;
    int4* c4 = (int4*)g_cnt;
    const int n4 = BATCH * NBUCK / 4;
    for (int e = i; e < n4; e += stride) { h4[e] = z; c4[e] = z; }
    if (i < BATCH) g_candcnt[i] = 0;
}

// ---------------- K1: keys + 16-bit bucket histogram ----------------
__global__ void k_keys_hist(const float* __restrict__ cls) {
    int g = blockIdx.x * blockDim.x + threadIdx.x;      // 0 .. BATCH*NPTS-1
    if (g >= BATCH * NPTS) return;
    int b = g >> 15, i = g & (NPTS - 1);
    const float* cp = cls + (size_t)g * NCLS;
    float s = fmaxf(fmaxf(cp[0], cp[1]), cp[2]);
    unsigned u = f2ord(s);
    unsigned long long key = ((unsigned long long)u << 32) |
                             (unsigned long long)(0xFFFFFFFFu - (unsigned)i);
    g_keyfull[b][i] = key;
    atomicAdd(&g_hist[b][u >> 16], 1);
}

// ---------------- K2: suffix-scan -> base[bucket], candcnt ----------------
// one block per batch, 1024 threads, 64 buckets per thread
__global__ void __launch_bounds__(1024)
k_scan_hist() {
    __shared__ int s[1024];
    __shared__ int smax;
    int b = blockIdx.x, t = threadIdx.x;
    if (t == 0) smax = 0;

    int h[64];
    int sum = 0;
    const int b0 = t * 64;
#pragma unroll
    for (int k = 0; k < 64; k++) { h[k] = g_hist[b][b0 + k]; sum += h[k]; }
    int own = sum;
    s[t] = sum;
    __syncthreads();
    // inclusive suffix scan (Hillis-Steele)
    for (int d = 1; d < 1024; d <<= 1) {
        int v = (t + d < 1024) ? s[t + d] : 0;
        __syncthreads();
        s[t] += v;
        __syncthreads();
    }
    int run = s[t] - own;            // elements in buckets > (t*64+63)
    int localmax = 0;
#pragma unroll
    for (int k = 63; k >= 0; k--) {
        g_base[b][b0 + k] = run;     // strictly-above count
        if (run < KSEL && h[k] > 0) {
            int e = run + h[k];
            if (e > localmax) localmax = e;
        }
        run += h[k];
    }
    if (localmax) atomicMax(&smax, localmax);
    __syncthreads();
    if (t == 0) g_candcnt[b] = smax;
}

// ---------------- K3: scatter candidates, bucket-grouped ----------------
__global__ void k_scatter() {
    int g = blockIdx.x * blockDim.x + threadIdx.x;
    if (g >= BATCH * NPTS) return;
    int b = g >> 15, i = g & (NPTS - 1);
    unsigned long long key = g_keyfull[b][i];
    int bucket = (int)(key >> 48);
    int base = g_base[b][bucket];
    if (base < KSEL) {
        int pos = atomicAdd(&g_cnt[b][bucket], 1);
        g_cand[b][base + pos] = key;       // base+pos < NPTS always
    }
}

// ---------------- K4: exact in-bucket rank -> g_topk ----------------
__global__ void k_rank() {
    int g = blockIdx.x * blockDim.x + threadIdx.x;
    if (g >= BATCH * NPTS) return;
    int b = g >> 15, slot = g & (NPTS - 1);
    if (slot >= g_candcnt[b]) return;
    unsigned long long key = g_cand[b][slot];
    int bucket = (int)(key >> 48);
    int segbase = g_base[b][bucket];
    int segcnt  = g_hist[b][bucket];
    int rank = segbase;
    if (segcnt > 1) {
        const unsigned long long* seg = &g_cand[b][segbase];
        int gt = 0;
        for (int m = 0; m < segcnt; m++) gt += (__ldg(&seg[m]) > key);
        rank += gt;                        // keys distinct -> unique ranks
    }
    if (rank < KSEL) g_topk[b][rank] = key;
}

// ---------------- gather top-4096 boxes + precompute IOU fields ----------------
__global__ void k_gather(const float* __restrict__ boxes,
                         const float* __restrict__ cls) {
    int g = blockIdx.x * blockDim.x + threadIdx.x;
    if (g >= BATCH * KSEL) return;
    int b = g >> 12, r = g & (KSEL - 1);
    unsigned long long key = g_topk[b][r];
    int idx = (int)(0xFFFFFFFFu - (unsigned)key);

    const float* bx = boxes + ((size_t)b * NPTS + idx) * 7;
    float v0 = bx[0], v1 = bx[1], v2 = bx[2], v3 = bx[3],
          v4 = bx[4], v5 = bx[5], v6 = bx[6];
    float* ro = &g_rois[b][r][0];
    ro[0] = v0; ro[1] = v1; ro[2] = v2; ro[3] = v3;
    ro[4] = v4; ro[5] = v5; ro[6] = v6;

    const float* cp = cls + ((size_t)b * NPTS + idx) * NCLS;
    float c0 = cp[0], c1 = cp[1], c2 = cp[2];
    float s = c0; int lab = 0;
    if (c1 > s) { s = c1; lab = 1; }
    if (c2 > s) { s = c2; lab = 2; }
    g_scores[b][r] = s;
    g_labels[b][r] = (unsigned char)lab;

    // match reference rounding exactly: x1 = x - 0.5*dx (mul then sub, no FMA)
    float hx = __fmul_rn(0.5f, v3), hy = __fmul_rn(0.5f, v4);
    float x1 = __fsub_rn(v0, hx), x2 = __fadd_rn(v0, hx);
    float y1 = __fsub_rn(v1, hy), y2 = __fadd_rn(v1, hy);
    g_box4[b][r] = make_float4(x1, y1, x2, y2);
    g_area[b][r] = __fmul_rn(v3, v4);
}

// ---------------- suppression bitmask ----------------
// stage 0: upper-triangular blocks within the first 1024 boxes
// stage 1: remaining blocks; whole batch early-exits when stage-0 sufficed
__global__ void __launch_bounds__(64)
k_mask(int stage) {
    int b = blockIdx.z;
    if (stage && g_done[b]) return;        // fast retire path first
    int cb = blockIdx.x, rb = blockIdx.y;
    if (cb < rb) return;
    if (stage && cb < NW1 && rb < NW1) return;

    __shared__ float4 sb[64];
    __shared__ float  sa[64];
    int t = threadIdx.x;
    sb[t] = g_box4[b][cb * 64 + t];
    sa[t] = g_area[b][cb * 64 + t];
    __syncthreads();

    int i = rb * 64 + t;
    float4 me = g_box4[b][i];
    float  a  = g_area[b][i];
    unsigned long long m = 0;
    int j0 = (cb == rb) ? (t + 1) : 0;     // only j > i suppressed
    for (int jj = j0; jj < 64; jj++) {
        float4 o = sb[jj];
        float ix = __fsub_rn(fminf(me.z, o.z), fmaxf(me.x, o.x));
        float iy = __fsub_rn(fminf(me.w, o.w), fmaxf(me.y, o.y));
        if (ix > 0.0f && iy > 0.0f) {      // rare: only then pay the divide
            float inter = __fmul_rn(ix, iy);
            float denom = __fadd_rn(__fsub_rn(__fadd_rn(a, sa[jj]), inter), 1e-6f);
            if (__fdiv_rn(inter, denom) > 0.7f) m |= (1ull << jj);
        }
    }
    g_mask[b][(size_t)i * NWORDS + cb] = m;
}

// ---------------- sequential greedy scan, word-chunked ----------------
__global__ void __launch_bounds__(64)
k_scan(int full) {
    int b = blockIdx.x, t = threadIdx.x;
    if (full && g_done[b]) return;
    const int NW = full ? NWORDS : NW1;

    __shared__ unsigned long long remv[NWORDS], acc_s[NWORDS], diag[64];
    remv[t] = 0ull;
    __syncthreads();

    for (int w = 0; w < NW; w++) {
        diag[t] = g_mask[b][(size_t)(w * 64 + t) * NWORDS + w];
        __syncthreads();
        if (t == w) {
            unsigned long long d[64];
#pragma unroll
            for (int q = 0; q < 64; q++) d[q] = diag[q];
            unsigned long long rem = remv[w], acc = 0ull;
#pragma unroll
            for (int bit = 0; bit < 64; bit++) {
                if (!((rem >> bit) & 1ull)) { acc |= (1ull << bit); rem |= d[bit]; }
            }
            acc_s[w] = acc;
        }
        __syncthreads();
        if (t > w && t < NW) {
            unsigned long long aa = acc_s[w];
            unsigned long long r = remv[t];
            while (aa) {
                int bit = __ffsll((long long)aa) - 1;
                aa &= aa - 1;
                r |= g_mask[b][(size_t)(w * 64 + bit) * NWORDS + t];
            }
            remv[t] = r;
        }
        __syncthreads();
    }

    g_accept[b][t] = (t < NW) ? acc_s[t] : 0ull;
    if (t == 0 && !full) {
        int cnt = 0;
        for (int w = 0; w < NW; w++) cnt += __popcll(acc_s[w]);
        g_done[b] = (cnt >= KPOST);
    }
}

// ---------------- output ----------------
__global__ void k_zero_out(float* out, int n) {
    int i = blockIdx.x * blockDim.x + threadIdx.x;
    if (i < n) out[i] = 0.0f;
}

__global__ void __launch_bounds__(64)
k_compact(float* __restrict__ out) {
    int b = blockIdx.x, t = threadIdx.x;
    __shared__ unsigned long long acc[NWORDS];
    __shared__ int pref[NWORDS];
    acc[t] = g_accept[b][t];
    __syncthreads();
    if (t == 0) {
        int s = 0;
        for (int w = 0; w < NWORDS; w++) { pref[w] = s; s += __popcll(acc[w]); }
    }
    __syncthreads();

    unsigned long long a = acc[t];
    int rank = pref[t];
    while (a && rank < KPOST) {
        int bit = __ffsll((long long)a) - 1;
        a &= a - 1;
        int i = t * 64 + bit;
        const float* ro = &g_rois[b][i][0];
        int obase = (b * KPOST + rank) * 7;
#pragma unroll
        for (int c = 0; c < 7; c++) out[obase + c] = ro[c];
        out[SC_OFF + b * KPOST + rank] = g_scores[b][i];
        out[LB_OFF + b * KPOST + rank] = (float)(g_labels[b][i] + 1);
        rank++;
    }
}

// ---------------- launch ----------------
extern "C" void kernel_launch(void* const* d_in, const int* in_sizes, int n_in,
                              void* d_out, int out_size) {
    const float* boxes = (const float*)d_in[0];
    const float* cls   = (const float*)d_in[1];
    if (n_in >= 2 && in_sizes[0] == BATCH * NPTS * NCLS) {
        boxes = (const float*)d_in[1];
        cls   = (const float*)d_in[0];
    }
    float* out = (float*)d_out;

    const int NTOT = BATCH * NPTS;

    // top-k selection (radix bucket + exact rank)
    k_zero_state<<<128, 256>>>();
    k_keys_hist<<<NTOT / 256, 256>>>(cls);
    k_scan_hist<<<BATCH, 1024>>>();
    k_scatter<<<NTOT / 256, 256>>>();
    k_rank<<<NTOT / 256, 256>>>();

    // gather + precompute
    k_gather<<<(BATCH * KSEL + 255) / 256, 256>>>(boxes, cls);

    // staged NMS: first 1024 boxes, then (rarely) the full 4096
    k_mask<<<dim3(NW1, NW1, BATCH), 64>>>(0);
    k_scan<<<BATCH, 64>>>(0);
    k_mask<<<dim3(NWORDS, NWORDS, BATCH), 64>>>(1);
    k_scan<<<BATCH, 64>>>(1);

    // outputs
    k_zero_out<<<(out_size + 255) / 256, 256>>>(out, out_size);
    k_compact<<<BATCH, 64>>>(out);
}

// round 4
// speedup vs baseline: 2.2993x; 1.7896x over previous
#include <cuda_runtime.h>
#include <cuda_bf16.h>

// ---------------- problem constants ----------------
#define BATCH   4
#define NPTS    32768
#define NCLS    3
#define KSEL    4096          // NMS_PRE_MAXSIZE
#define KPOST   512           // NMS_POST_MAXSIZE
#define NWORDS  64            // 4096 / 64
#define NW1     16            // first-stage scan: 1024 boxes
#define NBUCK   65536         // 16-bit score-radix buckets

#define ROIS_ELEMS   (BATCH * KPOST * 7)          // 14336
#define SC_OFF       (ROIS_ELEMS)                 // 14336
#define LB_OFF       (ROIS_ELEMS + BATCH * KPOST) // 16384

// ---------------- device scratch (no allocations allowed) ----------------
__device__ unsigned long long g_keyfull[BATCH][NPTS];       // 1 MB
__device__ unsigned long long g_cand[BATCH][NPTS];          // 1 MB (bucket-grouped)
__device__ unsigned long long g_topk[BATCH][KSEL];          // descending top-4096 keys
__device__ int                g_hist[BATCH][NBUCK];         // 1 MB
__device__ int                g_base[BATCH][NBUCK];         // 1 MB
__device__ int                g_cnt [BATCH][NBUCK];         // scatter offsets
__device__ int                g_candcnt[BATCH];

__device__ float4             g_box4[BATCH][KSEL];          // x1,y1,x2,y2
__device__ float              g_area[BATCH][KSEL];
__device__ float              g_rois[BATCH][KSEL][7];
__device__ float              g_scores[BATCH][KSEL];
__device__ unsigned char      g_labels[BATCH][KSEL];
__device__ unsigned long long g_mask[BATCH][KSEL * NWORDS]; // 8 MB
__device__ unsigned long long g_accept[BATCH][NWORDS];
__device__ int                g_done[BATCH];

// ---------------- order-preserving float->uint transform ----------------
__device__ __forceinline__ unsigned f2ord(float s) {
    unsigned u = __float_as_uint(s);
    return (u & 0x80000000u) ? ~u : (u | 0x80000000u);
}

// ---------------- Kz: zero per-replay state (vectorized) ----------------
__global__ void k_zero_state() {
    int i = blockIdx.x * blockDim.x + threadIdx.x;
    int stride = gridDim.x * blockDim.x;
    int4 z = make_int4(0, 0, 0, 0);
    int4* h4 = (int4*)g_hist;
    int4* c4 = (int4*)g_cnt;
    const int n4 = BATCH * NBUCK / 4;
    for (int e = i; e < n4; e += stride) { h4[e] = z; c4[e] = z; }
    if (i < BATCH) g_candcnt[i] = 0;
}

// ---------------- K1: keys + 16-bit bucket histogram ----------------
__global__ void k_keys_hist(const float* __restrict__ cls) {
    int g = blockIdx.x * blockDim.x + threadIdx.x;      // 0 .. BATCH*NPTS-1
    if (g >= BATCH * NPTS) return;
    int b = g >> 15, i = g & (NPTS - 1);
    const float* cp = cls + (size_t)g * NCLS;
    float s = fmaxf(fmaxf(cp[0], cp[1]), cp[2]);
    unsigned u = f2ord(s);
    unsigned long long key = ((unsigned long long)u << 32) |
                             (unsigned long long)(0xFFFFFFFFu - (unsigned)i);
    g_keyfull[b][i] = key;
    atomicAdd(&g_hist[b][u >> 16], 1);
}

// ---------------- K2: suffix-scan -> base[bucket], candcnt ----------------
__global__ void __launch_bounds__(1024)
k_scan_hist() {
    __shared__ int s[1024];
    __shared__ int smax;
    int b = blockIdx.x, t = threadIdx.x;
    if (t == 0) smax = 0;

    int h[64];
    int sum = 0;
    const int b0 = t * 64;
#pragma unroll
    for (int k = 0; k < 64; k++) { h[k] = g_hist[b][b0 + k]; sum += h[k]; }
    int own = sum;
    s[t] = sum;
    __syncthreads();
    for (int d = 1; d < 1024; d <<= 1) {
        int v = (t + d < 1024) ? s[t + d] : 0;
        __syncthreads();
        s[t] += v;
        __syncthreads();
    }
    int run = s[t] - own;            // elements in buckets > (t*64+63)
    int localmax = 0;
#pragma unroll
    for (int k = 63; k >= 0; k--) {
        g_base[b][b0 + k] = run;     // strictly-above count
        if (run < KSEL && h[k] > 0) {
            int e = run + h[k];
            if (e > localmax) localmax = e;
        }
        run += h[k];
    }
    if (localmax) atomicMax(&smax, localmax);
    __syncthreads();
    if (t == 0) g_candcnt[b] = smax;
}

// ---------------- K3: scatter candidates, bucket-grouped ----------------
__global__ void k_scatter() {
    int g = blockIdx.x * blockDim.x + threadIdx.x;
    if (g >= BATCH * NPTS) return;
    int b = g >> 15, i = g & (NPTS - 1);
    unsigned long long key = g_keyfull[b][i];
    int bucket = (int)(key >> 48);
    int base = g_base[b][bucket];
    if (base < KSEL) {
        int pos = atomicAdd(&g_cnt[b][bucket], 1);
        g_cand[b][base + pos] = key;
    }
}

// ---------------- K4: exact in-bucket rank -> g_topk ----------------
__global__ void k_rank() {
    int g = blockIdx.x * blockDim.x + threadIdx.x;
    if (g >= BATCH * NPTS) return;
    int b = g >> 15, slot = g & (NPTS - 1);
    if (slot >= g_candcnt[b]) return;
    unsigned long long key = g_cand[b][slot];
    int bucket = (int)(key >> 48);
    int segbase = g_base[b][bucket];
    int segcnt  = g_hist[b][bucket];
    int rank = segbase;
    if (segcnt > 1) {
        const unsigned long long* seg = &g_cand[b][segbase];
        int gt = 0;
        for (int m = 0; m < segcnt; m++) gt += (__ldg(&seg[m]) > key);
        rank += gt;                        // keys distinct -> unique ranks
    }
    if (rank < KSEL) g_topk[b][rank] = key;
}

// ---------------- gather top-4096 boxes + precompute IOU fields ----------------
__global__ void k_gather(const float* __restrict__ boxes,
                         const float* __restrict__ cls) {
    int g = blockIdx.x * blockDim.x + threadIdx.x;
    if (g >= BATCH * KSEL) return;
    int b = g >> 12, r = g & (KSEL - 1);
    unsigned long long key = g_topk[b][r];
    int idx = (int)(0xFFFFFFFFu - (unsigned)key);

    const float* bx = boxes + ((size_t)b * NPTS + idx) * 7;
    float v0 = bx[0], v1 = bx[1], v2 = bx[2], v3 = bx[3],
          v4 = bx[4], v5 = bx[5], v6 = bx[6];
    float* ro = &g_rois[b][r][0];
    ro[0] = v0; ro[1] = v1; ro[2] = v2; ro[3] = v3;
    ro[4] = v4; ro[5] = v5; ro[6] = v6;

    const float* cp = cls + ((size_t)b * NPTS + idx) * NCLS;
    float c0 = cp[0], c1 = cp[1], c2 = cp[2];
    float s = c0; int lab = 0;
    if (c1 > s) { s = c1; lab = 1; }
    if (c2 > s) { s = c2; lab = 2; }
    g_scores[b][r] = s;
    g_labels[b][r] = (unsigned char)lab;

    float hx = __fmul_rn(0.5f, v3), hy = __fmul_rn(0.5f, v4);
    float x1 = __fsub_rn(v0, hx), x2 = __fadd_rn(v0, hx);
    float y1 = __fsub_rn(v1, hy), y2 = __fadd_rn(v1, hy);
    g_box4[b][r] = make_float4(x1, y1, x2, y2);
    g_area[b][r] = __fmul_rn(v3, v4);
}

// ---------------- suppression bitmask ----------------
__global__ void __launch_bounds__(64)
k_mask(int stage) {
    int b = blockIdx.z;
    if (stage && g_done[b]) return;
    int cb = blockIdx.x, rb = blockIdx.y;
    if (cb < rb) return;
    if (stage && cb < NW1 && rb < NW1) return;

    __shared__ float4 sb[64];
    __shared__ float  sa[64];
    int t = threadIdx.x;
    sb[t] = g_box4[b][cb * 64 + t];
    sa[t] = g_area[b][cb * 64 + t];
    __syncthreads();

    int i = rb * 64 + t;
    float4 me = g_box4[b][i];
    float  a  = g_area[b][i];
    unsigned long long m = 0;
    int j0 = (cb == rb) ? (t + 1) : 0;
    for (int jj = j0; jj < 64; jj++) {
        float4 o = sb[jj];
        float ix = __fsub_rn(fminf(me.z, o.z), fmaxf(me.x, o.x));
        float iy = __fsub_rn(fminf(me.w, o.w), fmaxf(me.y, o.y));
        if (ix > 0.0f && iy > 0.0f) {
            float inter = __fmul_rn(ix, iy);
            float denom = __fadd_rn(__fsub_rn(__fadd_rn(a, sa[jj]), inter), 1e-6f);
            if (__fdiv_rn(inter, denom) > 0.7f) m |= (1ull << jj);
        }
    }
    g_mask[b][(size_t)i * NWORDS + cb] = m;
}

// ---------------- greedy scan: serial decisions, PARALLEL row-OR ----------------
// 1024 threads: (qg = tid>>6 in 0..15, col = tid&63). Per word w:
//   step A: 64 threads fetch diagonal block column w
//   step B: thread 0 runs the serial 64-bit greedy (only true serial part)
//   step C: all threads load the 64x64 mask block for word w in parallel
//           (4 coalesced rows each), mask rows by accept bits, OR-reduce
//           16 partials per column through smem into remv[col]
__global__ void __launch_bounds__(1024)
k_scan(int full) {
    int b = blockIdx.x;
    if (full && g_done[b]) return;
    const int NW = full ? NWORDS : NW1;

    int tid = threadIdx.x;
    int col = tid & 63;
    int qg  = tid >> 6;            // 0..15

    __shared__ unsigned long long remv[NWORDS];
    __shared__ unsigned long long acc_s[NWORDS];
    __shared__ unsigned long long diag[64];
    __shared__ unsigned long long part[16][64];

    if (tid < NWORDS) remv[tid] = 0ull;
    __syncthreads();

    for (int w = 0; w < NW; w++) {
        const unsigned long long* blk = &g_mask[b][(size_t)(w * 64) * NWORDS];

        // A: diagonal fetch (parallel, 64 threads)
        if (tid < 64) diag[tid] = blk[(size_t)tid * NWORDS + w];

        // C-prefetch: issue the block-row loads now; they don't depend on acc
        unsigned long long m0 = blk[(size_t)(qg     ) * NWORDS + col];
        unsigned long long m1 = blk[(size_t)(qg + 16) * NWORDS + col];
        unsigned long long m2 = blk[(size_t)(qg + 32) * NWORDS + col];
        unsigned long long m3 = blk[(size_t)(qg + 48) * NWORDS + col];
        __syncthreads();

        // B: serial greedy on thread 0 (smem reads software-pipelined)
        if (tid == 0) {
            unsigned long long rem = remv[w], acc = 0ull;
            unsigned long long dn = diag[0];
#pragma unroll
            for (int bit = 0; bit < 64; bit++) {
                unsigned long long d = dn;
                if (bit < 63) dn = diag[bit + 1];
                if (!((rem >> bit) & 1ull)) { acc |= (1ull << bit); rem |= d; }
            }
            acc_s[w] = acc;
        }
        __syncthreads();

        // C: mask preloaded rows by accept bits, two-level OR reduction
        unsigned long long acc = acc_s[w];
        unsigned long long p = 0ull;
        if ((acc >> (qg     )) & 1ull) p |= m0;
        if ((acc >> (qg + 16)) & 1ull) p |= m1;
        if ((acc >> (qg + 32)) & 1ull) p |= m2;
        if ((acc >> (qg + 48)) & 1ull) p |= m3;
        part[qg][col] = p;
        __syncthreads();

        if (tid < 64) {
            unsigned long long r = remv[tid];
#pragma unroll
            for (int k = 0; k < 16; k++) r |= part[k][tid];
            remv[tid] = r;
        }
        __syncthreads();
    }

    if (tid < NWORDS) g_accept[b][tid] = (tid < NW) ? acc_s[tid] : 0ull;
    if (tid == 0 && !full) {
        int cnt = 0;
        for (int w = 0; w < NW; w++) cnt += __popcll(acc_s[w]);
        g_done[b] = (cnt >= KPOST);
    }
}

// ---------------- output ----------------
__global__ void k_zero_out(float* out, int n) {
    int i = blockIdx.x * blockDim.x + threadIdx.x;
    if (i < n) out[i] = 0.0f;
}

__global__ void __launch_bounds__(64)
k_compact(float* __restrict__ out) {
    int b = blockIdx.x, t = threadIdx.x;
    __shared__ unsigned long long acc[NWORDS];
    __shared__ int pref[NWORDS];
    acc[t] = g_accept[b][t];
    __syncthreads();
    if (t == 0) {
        int s = 0;
        for (int w = 0; w < NWORDS; w++) { pref[w] = s; s += __popcll(acc[w]); }
    }
    __syncthreads();

    unsigned long long a = acc[t];
    int rank = pref[t];
    while (a && rank < KPOST) {
        int bit = __ffsll((long long)a) - 1;
        a &= a - 1;
        int i = t * 64 + bit;
        const float* ro = &g_rois[b][i][0];
        int obase = (b * KPOST + rank) * 7;
#pragma unroll
        for (int c = 0; c < 7; c++) out[obase + c] = ro[c];
        out[SC_OFF + b * KPOST + rank] = g_scores[b][i];
        out[LB_OFF + b * KPOST + rank] = (float)(g_labels[b][i] + 1);
        rank++;
    }
}

// ---------------- launch ----------------
extern "C" void kernel_launch(void* const* d_in, const int* in_sizes, int n_in,
                              void* d_out, int out_size) {
    const float* boxes = (const float*)d_in[0];
    const float* cls   = (const float*)d_in[1];
    if (n_in >= 2 && in_sizes[0] == BATCH * NPTS * NCLS) {
        boxes = (const float*)d_in[1];
        cls   = (const float*)d_in[0];
    }
    float* out = (float*)d_out;

    const int NTOT = BATCH * NPTS;

    // top-k selection (radix bucket + exact rank)
    k_zero_state<<<128, 256>>>();
    k_keys_hist<<<NTOT / 256, 256>>>(cls);
    k_scan_hist<<<BATCH, 1024>>>();
    k_scatter<<<NTOT / 256, 256>>>();
    k_rank<<<NTOT / 256, 256>>>();

    // gather + precompute
    k_gather<<<(BATCH * KSEL + 255) / 256, 256>>>(boxes, cls);

    // staged NMS: first 1024 boxes, then (rarely) the full 4096
    k_mask<<<dim3(NW1, NW1, BATCH), 64>>>(0);
    k_scan<<<BATCH, 1024>>>(0);
    k_mask<<<dim3(NWORDS, NWORDS, BATCH), 64>>>(1);
    k_scan<<<BATCH, 1024>>>(1);

    // outputs
    k_zero_out<<<(out_size + 255) / 256, 256>>>(out, out_size);
    k_compact<<<BATCH, 64>>>(out);
}